// round 5
// baseline (speedup 1.0000x reference)
#include <cuda_runtime.h>

typedef unsigned long long u64;

#define WW 512
#define HH 512
#define DD 64
#define NN 2
#define HS 8
#define SQRT2F 1.41421356237309515f

// Zero the scalar output (d_out is poisoned to 0xAA by the harness).
__global__ void hess_init_kernel(float* out) { out[0] = 0.0f; }

// ---- packed f32x2 helpers -------------------------------------------------
__device__ __forceinline__ u64 PK(float lo, float hi) {
    u64 r; asm("mov.b64 %0,{%1,%2};" : "=l"(r) : "f"(lo), "f"(hi)); return r;
}
__device__ __forceinline__ void UPK(u64 v, float& lo, float& hi) {
    asm("mov.b64 {%0,%1},%2;" : "=f"(lo), "=f"(hi) : "l"(v));
}
__device__ __forceinline__ u64 ADD2(u64 a, u64 b) {
    u64 r; asm("add.rn.f32x2 %0,%1,%2;" : "=l"(r) : "l"(a), "l"(b)); return r;
}
__device__ __forceinline__ u64 FMA2(u64 a, u64 b, u64 c) {  // a*b + c
    u64 r; asm("fma.rn.f32x2 %0,%1,%2,%3;" : "=l"(r) : "l"(a), "l"(b), "l"(c)); return r;
}
#define NEG1_2 0xBF800000BF800000ULL                  /* (-1.f,-1.f) */
__device__ __forceinline__ u64 SUB2(u64 a, u64 b) {   // a - b
    return FMA2(b, NEG1_2, a);
}
__device__ __forceinline__ u64 ABS2(u64 a) {          // |lo|,|hi| on ALU pipe
    return a & 0x7FFFFFFF7FFFFFFFULL;
}

// ---- interior strip: packed math, fully unrolled --------------------------
__device__ __forceinline__ float strip_sum_int(
    const float* __restrict__ p0, const float* __restrict__ p1,
    const float* __restrict__ p2, int h0, int w0, float wzz, bool lastw)
{
    const u64 W2   = PK(2.0f, 2.0f);
    const u64 WRT2 = PK(SQRT2F, SQRT2F);
    const u64 WZZ2 = PK(wzz, wzz);

    const int hw2 = lastw ? (WW - 2) : (w0 + 4);  // float2 halo (clamped for tid127)
    const int hw1 = lastw ? (WW - 1) : (w0 + 4);  // scalar halo

    const float* ra = p0 + h0 * WW;   // slab d,   row h0
    const float* rp = p1 + h0 * WW;   // slab d+1, row h0
    const float* rq = p2 + h0 * WW;   // slab d+2, row h0

    // preload rolling rows: A=(d,h0), B=(d,h0+1), P=(d+1,h0)
    float4 Av = *(const float4*)(ra + w0);
    float2 ah = *(const float2*)(ra + hw2);
    float4 Bv = *(const float4*)(ra + WW + w0);
    float2 bh = *(const float2*)(ra + WW + hw2);
    float4 Pv = *(const float4*)(rp + w0);
    float  p4 = rp[hw1];

    u64 A01 = PK(Av.x, Av.y), A23 = PK(Av.z, Av.w);
    u64 B01 = PK(Bv.x, Bv.y), B23 = PK(Bv.z, Bv.w);
    u64 P01 = PK(Pv.x, Pv.y), P23 = PK(Pv.z, Pv.w);
    float a4 = ah.x, a5 = ah.y, b4 = bh.x, b5 = bh.y;

    // rolling y-difference u = row(h) - row(h+1) of slab d
    u64 u01 = SUB2(A01, B01), u23 = SUB2(A23, B23);
    float u4 = a4 - b4;

    u64 acc01 = 0ULL, acc23 = 0ULL;   // (+0,+0)

    #pragma unroll
    for (int j = 0; j < HS; ++j) {
        const float4 Cv = *(const float4*)(ra + (j + 2) * WW + w0);
        const float2 ch = *(const float2*)(ra + (j + 2) * WW + hw2);
        const float4 Rv = *(const float4*)(rp + (j + 1) * WW + w0);
        const float  r4 = (rp + (j + 1) * WW)[hw1];
        const float4 Qv = *(const float4*)(rq + j * WW + w0);

        const u64 C01 = PK(Cv.x, Cv.y), C23 = PK(Cv.z, Cv.w);
        const u64 R01 = PK(Rv.x, Rv.y), R23 = PK(Rv.z, Rv.w);
        const u64 Q01 = PK(Qv.x, Qv.y), Q23 = PK(Qv.z, Qv.w);

        // scalar views of rolling state (register aliases after copy-prop)
        float a0, a1, a2, a3;  UPK(A01, a0, a1);  UPK(A23, a2, a3);
        float uu0, uu1, uu2, uu3;  UPK(u01, uu0, uu1);  UPK(u23, uu2, uu3);

        // x-differences of row A (scalar; feeds shifted packs)
        float dx0 = a0 - a1, dx1 = a1 - a2, dx2 = a2 - a3;
        float dx3 = a3 - a4, dx4 = a4 - a5;
        // w-edge fixes (tid 127 only; predicated, uniform): invalid shifted
        // terms become |t - t| = 0 exactly.
        if (lastw) { dx3 = dx2; dx4 = dx2; }
        const float xu4 = lastw ? uu3 : u4;

        // shared packed differences
        const u64 un01 = SUB2(B01, C01), un23 = SUB2(B23, C23);
        const float un4 = b4 - ch.x;
        const u64 v01 = SUB2(A01, P01), v23 = SUB2(A23, P23);
        float v0, v1, v2, v3;  UPK(v01, v0, v1);  UPK(v23, v2, v3);
        const float xv4 = lastw ? v3 : (a4 - p4);
        const u64 z01 = SUB2(P01, Q01), z23 = SUB2(P23, Q23);
        const u64 s01 = SUB2(P01, R01), s23 = SUB2(P23, R23);

        // g_xx (weight 1)
        acc01 = ADD2(acc01, ABS2(SUB2(PK(dx0, dx1), PK(dx1, dx2))));
        acc23 = ADD2(acc23, ABS2(SUB2(PK(dx2, dx3), PK(dx3, dx4))));
        // g_yy (weight 1)
        acc01 = ADD2(acc01, ABS2(SUB2(u01, un01)));
        acc23 = ADD2(acc23, ABS2(SUB2(u23, un23)));
        // g_zz (weight wzz = CONTIZ^2, zero at d edge)
        acc01 = FMA2(ABS2(SUB2(v01, z01)), WZZ2, acc01);
        acc23 = FMA2(ABS2(SUB2(v23, z23)), WZZ2, acc23);
        // g_xy (weight 2)
        acc01 = FMA2(ABS2(SUB2(u01, PK(uu1, uu2))), W2, acc01);
        acc23 = FMA2(ABS2(SUB2(u23, PK(uu3, xu4))), W2, acc23);
        // g_xz (weight 2*CONTIZ = sqrt2)
        acc01 = FMA2(ABS2(SUB2(v01, PK(v1, v2))), WRT2, acc01);
        acc23 = FMA2(ABS2(SUB2(v23, PK(v3, xv4))), WRT2, acc23);
        // g_yz (weight 2*CONTIZ = sqrt2)
        acc01 = FMA2(ABS2(SUB2(u01, s01)), WRT2, acc01);
        acc23 = FMA2(ABS2(SUB2(u23, s23)), WRT2, acc23);

        // roll rows + halos + u (register renames under full unroll)
        A01 = B01; A23 = B23; a4 = b4; a5 = b5;
        B01 = C01; B23 = C23; b4 = ch.x; b5 = ch.y;
        P01 = R01; P23 = R23; p4 = r4;
        u01 = un01; u23 = un23; u4 = un4;
    }

    float s0, s1, s2, s3;
    UPK(acc01, s0, s1); UPK(acc23, s2, s3);
    return (s0 + s1) + (s2 + s3);
}

// ---- boundary strip (last h-strip, 1/64 blocks): proven scalar path -------
__device__ __forceinline__ float strip_sum_bnd(
    const float* __restrict__ p0, const float* __restrict__ p1,
    const float* __restrict__ p2, int h0, int w0, float wzz)
{
    const int hw2 = (w0 + 5 < WW) ? (w0 + 4) : (WW - 2);
    const int hw1 = (w0 + 4 < WW) ? (w0 + 4) : (WW - 1);

    float wxx[4], wxy[4], wxz[4];
    #pragma unroll
    for (int i = 0; i < 4; ++i) {
        const int wi = w0 + i;
        wxx[i] = (wi <= WW - 3) ? 1.0f   : 0.0f;
        wxy[i] = (wi <= WW - 2) ? 2.0f   : 0.0f;
        wxz[i] = (wi <= WW - 2) ? SQRT2F : 0.0f;
    }

    const float* ra  = p0 + h0 * WW;
    const float* rp  = p1 + h0 * WW;
    const float* rq0 = p2 + h0 * WW;

    float4 A  = *(const float4*)(ra + w0);
    float2 ah = *(const float2*)(ra + hw2);
    float4 B  = *(const float4*)(ra + WW + w0);
    float2 bh = *(const float2*)(ra + WW + hw2);
    float4 P  = *(const float4*)(rp + w0);
    float  p4 = rp[hw1];
    float a4 = ah.x, a5 = ah.y, b4 = bh.x, b5 = bh.y;

    float u[5];
    u[0] = A.x - B.x; u[1] = A.y - B.y; u[2] = A.z - B.z; u[3] = A.w - B.w;
    u[4] = a4 - b4;

    float acc0 = 0.0f, acc1 = 0.0f;

    #pragma unroll
    for (int j = 0; j < HS; ++j) {
        int ec = 0, er = 0;
        float wh2 = 1.0f, wh1 = 1.0f;
        if (j >= HS - 2) { ec = j - (HS - 3); wh2 = 0.0f; }
        if (j >= HS - 1) { er = 1;            wh1 = 0.0f; }
        const float* rc  = ra  + (j + 2 - ec) * WW;
        const float* rr  = rp  + (j + 1 - er) * WW;
        const float* rqj = rq0 + j * WW;

        float4 C  = *(const float4*)(rc + w0);
        float2 ch = *(const float2*)(rc + hw2);
        float4 R  = *(const float4*)(rr + w0);
        float  r4 = rr[hw1];
        float4 Q  = *(const float4*)(rqj + w0);

        float un[5], v[5], z[4], s[4], dx[5];
        un[0] = B.x - C.x; un[1] = B.y - C.y; un[2] = B.z - C.z; un[3] = B.w - C.w;
        un[4] = b4 - ch.x;
        v[0] = A.x - P.x; v[1] = A.y - P.y; v[2] = A.z - P.z; v[3] = A.w - P.w;
        v[4] = a4 - p4;
        z[0] = P.x - Q.x; z[1] = P.y - Q.y; z[2] = P.z - Q.z; z[3] = P.w - Q.w;
        s[0] = P.x - R.x; s[1] = P.y - R.y; s[2] = P.z - R.z; s[3] = P.w - R.w;
        dx[0] = A.x - A.y; dx[1] = A.y - A.z; dx[2] = A.z - A.w;
        dx[3] = A.w - a4;  dx[4] = a4 - a5;

        const float wyy = wh2;
        const float wyz = SQRT2F * wh1;

        #pragma unroll
        for (int i = 0; i < 4; ++i) {
            const float wxyi = wxy[i] * wh1;
            acc0 = fmaf(wxx[i], fabsf(dx[i] - dx[i + 1]), acc0);
            acc1 = fmaf(wyy,    fabsf(u[i]  - un[i]),     acc1);
            acc0 = fmaf(wzz,    fabsf(v[i]  - z[i]),      acc0);
            acc1 = fmaf(wxyi,   fabsf(u[i]  - u[i + 1]),  acc1);
            acc0 = fmaf(wxz[i], fabsf(v[i]  - v[i + 1]),  acc0);
            acc1 = fmaf(wyz,    fabsf(u[i]  - s[i]),      acc1);
        }

        A = B; B = C;
        a4 = b4; a5 = b5; b4 = ch.x; b5 = ch.y;
        P = R; p4 = r4;
        u[0] = un[0]; u[1] = un[1]; u[2] = un[2]; u[3] = un[3]; u[4] = un[4];
    }
    return acc0 + acc1;
}

__global__ __launch_bounds__(128, 7)
void hess_kernel(const float* __restrict__ x, float* __restrict__ out) {
    const int tid = threadIdx.x;
    const int lane = tid & 31;
    const int w0 = tid << 2;                 // 128 * 4 = 512 = WW
    const int h0 = blockIdx.x * HS;
    const int d  = blockIdx.y;
    const int n  = blockIdx.z;

    const size_t slab = (size_t)HH * WW;
    const float* p0 = x + (size_t)(n * DD + d) * slab;
    const bool hd1 = (d + 1 < DD);
    const bool hd2 = (d + 2 < DD);
    const float* p1 = p0 + (hd1 ? slab : 0);  // clamped: auto-zeroes xz/yz edge terms
    const float* p2 = p1 + (hd2 ? slab : 0);
    const float wzz = hd2 ? 0.5f : 0.0f;      // CONTIZ^2, masks g_zz at d edge

    float acc;
    if (blockIdx.x != (HH / HS - 1))
        acc = strip_sum_int(p0, p1, p2, h0, w0, wzz, tid == 127);
    else
        acc = strip_sum_bnd(p0, p1, p2, h0, w0, wzz);

    // ---- reduction: warp -> block -> global atomic ----
    acc += __shfl_xor_sync(0xffffffffu, acc, 16);
    acc += __shfl_xor_sync(0xffffffffu, acc, 8);
    acc += __shfl_xor_sync(0xffffffffu, acc, 4);
    acc += __shfl_xor_sync(0xffffffffu, acc, 2);
    acc += __shfl_xor_sync(0xffffffffu, acc, 1);

    __shared__ float warpsum[4];
    if (lane == 0) warpsum[tid >> 5] = acc;
    __syncthreads();
    if (tid == 0) {
        const float total = warpsum[0] + warpsum[1] + warpsum[2] + warpsum[3];
        atomicAdd(out, total * (1.0f / ((float)HH * (float)WW)));
    }
}

extern "C" void kernel_launch(void* const* d_in, const int* in_sizes, int n_in,
                              void* d_out, int out_size) {
    const float* img = (const float*)d_in[0];
    float* out = (float*)d_out;
    (void)in_sizes; (void)n_in; (void)out_size;

    hess_init_kernel<<<1, 1>>>(out);
    dim3 grid(HH / HS, DD, NN);   // 64 x 64 x 2 = 8192 blocks
    hess_kernel<<<grid, 128>>>(img, out);
}

// round 6
// speedup vs baseline: 1.0548x; 1.0548x over previous
#include <cuda_runtime.h>

#define WW 512
#define HH 512
#define DD 64
#define NN 2
#define HS 8
#define SQRT2F 1.41421356237309515f
#define NBLK ((HH / HS) * DD * NN)   /* 8192 */

// ---- rt-1 FFMA-imm helpers -------------------------------------------------
// a - b as fma(b, -1.0, a): FFMA with immediate multiplier issues at rt_SMSP=1
// (vs FADD rt 2). Bit-identical to FADD (product is exact).
__device__ __forceinline__ float FS(float a, float b) {
    float r;
    asm("fma.rn.f32 %0, %1, 0fBF800000, %2;" : "=f"(r) : "f"(b), "f"(a));
    return r;
}
// acc += a * IMM with IMM a PTX literal -> FFMA-imm rt 1 (abs of a folds into |Ra|).
#define FMAI(acc, a, IMM) \
    asm("fma.rn.f32 %0, %1, " IMM ", %0;" : "+f"(acc) : "f"(a))
#define IMM_1   "0f3F800000"
#define IMM_2   "0f40000000"
#define IMM_H   "0f3F000000"
#define IMM_RT2 "0f3FB504F3"

// ---- single-kernel finish scratch (graph-safe, deterministic per call) -----
__device__ float    g_acc = 0.0f;
__device__ unsigned g_cnt = 0;

// ---- interior strip: all-immediate weights, fully unrolled ------------------
// w-edge (tid 127) via input clamping: invalid shifted terms become |t-t| = 0.
// d-edges: HD2=false omits g_zz; xz/yz self-cancel through clamped pointers.
template<bool HD2>
__device__ __forceinline__ float strip_int(
    const float* __restrict__ p0, const float* __restrict__ p1,
    const float* __restrict__ p2, int h0, int w0, bool lastw)
{
    const int hw2 = lastw ? (WW - 2) : (w0 + 4);  // float2 halo (clamped tid127)
    const int hw1 = lastw ? (WW - 1) : (w0 + 4);  // scalar halo

    const float* ra = p0 + h0 * WW;   // slab d,   row h0
    const float* rp = p1 + h0 * WW;   // slab d+1, row h0
    const float* rq = p2 + h0 * WW;   // slab d+2, row h0

    float4 A  = *(const float4*)(ra + w0);
    float2 ah = *(const float2*)(ra + hw2);
    float4 B  = *(const float4*)(ra + WW + w0);
    float2 bh = *(const float2*)(ra + WW + hw2);
    float4 P  = *(const float4*)(rp + w0);
    float  p4 = rp[hw1];
    float a4 = ah.x, a5 = ah.y, b4 = bh.x, b5 = bh.y;

    // rolling y-difference u = row(h) - row(h+1) of slab d
    float u[5];
    u[0] = FS(A.x, B.x); u[1] = FS(A.y, B.y); u[2] = FS(A.z, B.z);
    u[3] = FS(A.w, B.w); u[4] = FS(a4, b4);

    float acc0 = 0.0f, acc1 = 0.0f, acc2 = 0.0f, acc3 = 0.0f;

    #pragma unroll
    for (int j = 0; j < HS; ++j) {
        const float4 C  = *(const float4*)(ra + (j + 2) * WW + w0);
        const float2 ch = *(const float2*)(ra + (j + 2) * WW + hw2);
        const float4 R  = *(const float4*)(rp + (j + 1) * WW + w0);
        const float  r4 = (rp + (j + 1) * WW)[hw1];
        float4 Q;
        if (HD2) Q = *(const float4*)(rq + j * WW + w0);

        // x-differences of row A (tid127: clamp so edge terms cancel to 0)
        float dx[5];
        dx[0] = FS(A.x, A.y); dx[1] = FS(A.y, A.z); dx[2] = FS(A.z, A.w);
        dx[3] = lastw ? dx[2] : FS(A.w, a4);
        dx[4] = lastw ? dx[2] : FS(a4, a5);

        float un[5];
        un[0] = FS(B.x, C.x); un[1] = FS(B.y, C.y); un[2] = FS(B.z, C.z);
        un[3] = FS(B.w, C.w); un[4] = FS(b4, ch.x);

        float v[5];
        v[0] = FS(A.x, P.x); v[1] = FS(A.y, P.y); v[2] = FS(A.z, P.z);
        v[3] = FS(A.w, P.w);
        v[4] = lastw ? v[3] : FS(a4, p4);

        float s[4];
        s[0] = FS(P.x, R.x); s[1] = FS(P.y, R.y); s[2] = FS(P.z, R.z);
        s[3] = FS(P.w, R.w);

        float ux4 = lastw ? u[3] : u[4];   // clamped shifted-u for g_xy i=3

        float z[4];
        if (HD2) {
            z[0] = FS(P.x, Q.x); z[1] = FS(P.y, Q.y);
            z[2] = FS(P.z, Q.z); z[3] = FS(P.w, Q.w);
        }

        #pragma unroll
        for (int i = 0; i < 4; ++i) {
            const float ui1 = (i < 3) ? u[i + 1] : ux4;
            FMAI(acc0, fabsf(FS(dx[i], dx[i + 1])), IMM_1);   // g_xx
            FMAI(acc1, fabsf(FS(u[i],  un[i])),     IMM_1);   // g_yy
            if (HD2)
                FMAI(acc2, fabsf(FS(v[i], z[i])),   IMM_H);   // g_zz * 0.5
            FMAI(acc3, fabsf(FS(u[i],  ui1)),       IMM_2);   // g_xy * 2
            FMAI(acc2, fabsf(FS(v[i],  v[i + 1])),  IMM_RT2); // g_xz * sqrt2
            FMAI(acc1, fabsf(FS(u[i],  s[i])),      IMM_RT2); // g_yz * sqrt2
        }

        // roll rows + halos + u (pure register renames under full unroll)
        A = B; B = C;
        a4 = b4; a5 = b5; b4 = ch.x; b5 = ch.y;
        P = R; p4 = r4;
        u[0] = un[0]; u[1] = un[1]; u[2] = un[2]; u[3] = un[3]; u[4] = un[4];
    }
    return (acc0 + acc1) + (acc2 + acc3);
}

// ---- boundary strip (last h-strip, 1/64 blocks): proven scalar path --------
__device__ __forceinline__ float strip_bnd(
    const float* __restrict__ p0, const float* __restrict__ p1,
    const float* __restrict__ p2, int h0, int w0, float wzz)
{
    const int hw2 = (w0 + 5 < WW) ? (w0 + 4) : (WW - 2);
    const int hw1 = (w0 + 4 < WW) ? (w0 + 4) : (WW - 1);

    float wxx[4], wxy[4], wxz[4];
    #pragma unroll
    for (int i = 0; i < 4; ++i) {
        const int wi = w0 + i;
        wxx[i] = (wi <= WW - 3) ? 1.0f   : 0.0f;
        wxy[i] = (wi <= WW - 2) ? 2.0f   : 0.0f;
        wxz[i] = (wi <= WW - 2) ? SQRT2F : 0.0f;
    }

    const float* ra  = p0 + h0 * WW;
    const float* rp  = p1 + h0 * WW;
    const float* rq0 = p2 + h0 * WW;

    float4 A  = *(const float4*)(ra + w0);
    float2 ah = *(const float2*)(ra + hw2);
    float4 B  = *(const float4*)(ra + WW + w0);
    float2 bh = *(const float2*)(ra + WW + hw2);
    float4 P  = *(const float4*)(rp + w0);
    float  p4 = rp[hw1];
    float a4 = ah.x, a5 = ah.y, b4 = bh.x, b5 = bh.y;

    float u[5];
    u[0] = A.x - B.x; u[1] = A.y - B.y; u[2] = A.z - B.z; u[3] = A.w - B.w;
    u[4] = a4 - b4;

    float acc0 = 0.0f, acc1 = 0.0f;

    #pragma unroll
    for (int j = 0; j < HS; ++j) {
        int ec = 0, er = 0;
        float wh2 = 1.0f, wh1 = 1.0f;
        if (j >= HS - 2) { ec = j - (HS - 3); wh2 = 0.0f; }
        if (j >= HS - 1) { er = 1;            wh1 = 0.0f; }
        const float* rc  = ra  + (j + 2 - ec) * WW;
        const float* rr  = rp  + (j + 1 - er) * WW;
        const float* rqj = rq0 + j * WW;

        float4 C  = *(const float4*)(rc + w0);
        float2 ch = *(const float2*)(rc + hw2);
        float4 R  = *(const float4*)(rr + w0);
        float  r4 = rr[hw1];
        float4 Q  = *(const float4*)(rqj + w0);

        float un[5], v[5], z[4], s[4], dx[5];
        un[0] = B.x - C.x; un[1] = B.y - C.y; un[2] = B.z - C.z; un[3] = B.w - C.w;
        un[4] = b4 - ch.x;
        v[0] = A.x - P.x; v[1] = A.y - P.y; v[2] = A.z - P.z; v[3] = A.w - P.w;
        v[4] = a4 - p4;
        z[0] = P.x - Q.x; z[1] = P.y - Q.y; z[2] = P.z - Q.z; z[3] = P.w - Q.w;
        s[0] = P.x - R.x; s[1] = P.y - R.y; s[2] = P.z - R.z; s[3] = P.w - R.w;
        dx[0] = A.x - A.y; dx[1] = A.y - A.z; dx[2] = A.z - A.w;
        dx[3] = A.w - a4;  dx[4] = a4 - a5;

        const float wyy = wh2;
        const float wyz = SQRT2F * wh1;

        #pragma unroll
        for (int i = 0; i < 4; ++i) {
            const float wxyi = wxy[i] * wh1;
            acc0 = fmaf(wxx[i], fabsf(dx[i] - dx[i + 1]), acc0);
            acc1 = fmaf(wyy,    fabsf(u[i]  - un[i]),     acc1);
            acc0 = fmaf(wzz,    fabsf(v[i]  - z[i]),      acc0);
            acc1 = fmaf(wxyi,   fabsf(u[i]  - u[i + 1]),  acc1);
            acc0 = fmaf(wxz[i], fabsf(v[i]  - v[i + 1]),  acc0);
            acc1 = fmaf(wyz,    fabsf(u[i]  - s[i]),      acc1);
        }

        A = B; B = C;
        a4 = b4; a5 = b5; b4 = ch.x; b5 = ch.y;
        P = R; p4 = r4;
        u[0] = un[0]; u[1] = un[1]; u[2] = un[2]; u[3] = un[3]; u[4] = un[4];
    }
    return acc0 + acc1;
}

__global__ __launch_bounds__(128, 8)
void hess_kernel(const float* __restrict__ x, float* __restrict__ out) {
    const int tid = threadIdx.x;
    const int lane = tid & 31;
    const int w0 = tid << 2;                 // 128 * 4 = 512 = WW
    const int h0 = blockIdx.x * HS;
    const int d  = blockIdx.y;
    const int n  = blockIdx.z;

    const size_t slab = (size_t)HH * WW;
    const float* p0 = x + (size_t)(n * DD + d) * slab;
    const bool hd1 = (d + 1 < DD);
    const bool hd2 = (d + 2 < DD);
    const float* p1 = p0 + (hd1 ? slab : 0);  // clamped: auto-zeroes xz/yz edge terms
    const float* p2 = p1 + (hd2 ? slab : 0);

    float acc;
    if (blockIdx.x != (HH / HS - 1)) {
        if (hd2) acc = strip_int<true >(p0, p1, p2, h0, w0, tid == 127);
        else     acc = strip_int<false>(p0, p1, p2, h0, w0, tid == 127);
    } else {
        acc = strip_bnd(p0, p1, p2, h0, w0, hd2 ? 0.5f : 0.0f);
    }

    // ---- reduction: warp -> block -> device scratch -> last block writes ----
    acc += __shfl_xor_sync(0xffffffffu, acc, 16);
    acc += __shfl_xor_sync(0xffffffffu, acc, 8);
    acc += __shfl_xor_sync(0xffffffffu, acc, 4);
    acc += __shfl_xor_sync(0xffffffffu, acc, 2);
    acc += __shfl_xor_sync(0xffffffffu, acc, 1);

    __shared__ float warpsum[4];
    if (lane == 0) warpsum[tid >> 5] = acc;
    __syncthreads();
    if (tid == 0) {
        const float bsum = warpsum[0] + warpsum[1] + warpsum[2] + warpsum[3];
        atomicAdd(&g_acc, bsum);
        __threadfence();
        const unsigned old = atomicInc(&g_cnt, NBLK - 1);  // wraps to 0 on last
        if (old == NBLK - 1) {
            const float total = atomicExch(&g_acc, 0.0f);  // read + reset for next replay
            out[0] = total * (1.0f / ((float)HH * (float)WW));
        }
    }
}

extern "C" void kernel_launch(void* const* d_in, const int* in_sizes, int n_in,
                              void* d_out, int out_size) {
    const float* img = (const float*)d_in[0];
    float* out = (float*)d_out;
    (void)in_sizes; (void)n_in; (void)out_size;

    dim3 grid(HH / HS, DD, NN);   // 64 x 64 x 2 = 8192 blocks
    hess_kernel<<<grid, 128>>>(img, out);
}